// round 1
// baseline (speedup 1.0000x reference)
#include <cuda_runtime.h>

// Problem constants
constexpr int B   = 4;
constexpr int N   = 1024;
constexpr int Dm  = 1024;
constexpr int H   = 16;
constexpr int DK  = 64;
constexpr int MRP = 32;
constexpr int NR  = 2 * MRP + 1;   // 65
constexpr int BH  = B * H;         // 64
constexpr float SCALE = 0.125f;    // 1/sqrt(64)

// Scratch (static device globals; no allocation allowed)
__device__ float g_Q[BH * N * DK];
__device__ float g_K[BH * N * DK];
__device__ float g_V[BH * N * DK];
__device__ float g_ctx[BH * N * DK];

#define F4E(v, j) ((j) == 0 ? (v).x : (j) == 1 ? (v).y : (j) == 2 ? (v).z : (v).w)

// ---------------------------------------------------------------------------
// Kernel 1: QKV projections.  Y = X @ W^T + b, scattered to head-major
// [bh][n][dk].  Tiled SGEMM 64x64x16, 256 threads, 4x4 micro-tile.
// ---------------------------------------------------------------------------
__global__ __launch_bounds__(256) void qkv_kernel(
    const float* __restrict__ q_in, const float* __restrict__ k_in,
    const float* __restrict__ v_in,
    const float* __restrict__ Wq, const float* __restrict__ bq,
    const float* __restrict__ Wk, const float* __restrict__ bk,
    const float* __restrict__ Wv, const float* __restrict__ bv)
{
    const int which = blockIdx.z;
    const float* X    = which == 0 ? q_in : which == 1 ? k_in : v_in;
    const float* W    = which == 0 ? Wq   : which == 1 ? Wk   : Wv;
    const float* bias = which == 0 ? bq   : which == 1 ? bk   : bv;
    float* out        = which == 0 ? g_Q  : which == 1 ? g_K  : g_V;

    __shared__ float As[16][72];
    __shared__ float Bs[16][72];

    const int m0 = blockIdx.x * 64;
    const int n0 = blockIdx.y * 64;
    const int tid = threadIdx.x;
    const int tx = tid & 15;       // n direction
    const int ty = tid >> 4;       // m direction
    const int lr = tid >> 2;       // load row (0..63)
    const int lc = tid & 3;        // load float4 col group (0..3)

    float acc[4][4] = {};

    for (int k0 = 0; k0 < Dm; k0 += 16) {
        float4 a  = *reinterpret_cast<const float4*>(&X[(size_t)(m0 + lr) * Dm + k0 + lc * 4]);
        float4 bw = *reinterpret_cast<const float4*>(&W[(size_t)(n0 + lr) * Dm + k0 + lc * 4]);
        __syncthreads();
        As[lc * 4 + 0][lr] = a.x;  As[lc * 4 + 1][lr] = a.y;
        As[lc * 4 + 2][lr] = a.z;  As[lc * 4 + 3][lr] = a.w;
        Bs[lc * 4 + 0][lr] = bw.x; Bs[lc * 4 + 1][lr] = bw.y;
        Bs[lc * 4 + 2][lr] = bw.z; Bs[lc * 4 + 3][lr] = bw.w;
        __syncthreads();
        #pragma unroll
        for (int kk = 0; kk < 16; kk++) {
            float4 av = *reinterpret_cast<const float4*>(&As[kk][ty * 4]);
            float4 bv4 = *reinterpret_cast<const float4*>(&Bs[kk][tx * 4]);
            #pragma unroll
            for (int i = 0; i < 4; i++) {
                const float aa = F4E(av, i);
                acc[i][0] += aa * bv4.x;
                acc[i][1] += aa * bv4.y;
                acc[i][2] += aa * bv4.z;
                acc[i][3] += aa * bv4.w;
            }
        }
    }

    const int o0 = n0 + tx * 4;
    const int h  = o0 >> 6;
    const int dk = o0 & 63;
    float4 bb = *reinterpret_cast<const float4*>(&bias[o0]);
    #pragma unroll
    for (int i = 0; i < 4; i++) {
        const int m = m0 + ty * 4 + i;
        const int b = m >> 10;
        const int n = m & 1023;
        float4 r;
        r.x = acc[i][0] + bb.x;
        r.y = acc[i][1] + bb.y;
        r.z = acc[i][2] + bb.z;
        r.w = acc[i][3] + bb.w;
        *reinterpret_cast<float4*>(&out[(size_t)((b * H + h) * N + n) * DK + dk]) = r;
    }
}

// ---------------------------------------------------------------------------
// Kernel 2: fused attention per (bh, 32-row q-tile).
// Full score row in SMEM, exact softmax, writes attn, computes ctx.
// ---------------------------------------------------------------------------
constexpr int TQ = 32;
constexpr int SP = 1032;   // sS row pitch in floats (pad: 1032 % 32 == 8)

constexpr int O_S  = 0;
constexpr int O_KV = O_S  + TQ * SP;   // 33024   (8192 floats: K^T [64][128] or V [128][64])
constexpr int O_Q  = O_KV + 8192;      // 41216   (32 x 64)
constexpr int O_RK = O_Q  + 2048;      // 43264   (65 x 64)
constexpr int O_RV = O_RK + 4160;      // 47424   (65 x 64)
constexpr int O_QR = O_RV + 4160;      // 51584   (32 x 65)
constexpr int O_AR = O_QR + 2080;      // 53664   (32 x 65)
constexpr int SMEM_FLOATS = O_AR + 2080; // 55744 floats = 222976 bytes

__global__ __launch_bounds__(256) void attn_kernel(
    const float* __restrict__ relK, const float* __restrict__ relV,
    float* __restrict__ attn_out)
{
    extern __shared__ float sm[];
    float* sS  = sm + O_S;
    float* sKV = sm + O_KV;
    float* sQ  = sm + O_Q;
    float* sRK = sm + O_RK;
    float* sRV = sm + O_RV;
    float* sQr = sm + O_QR;
    float* sAr = sm + O_AR;

    const int bh = blockIdx.y;
    const int q0 = blockIdx.x * TQ;
    const int tid  = threadIdx.x;
    const int warp = tid >> 5;
    const int lane = tid & 31;

    // ---- load Q tile and rel embeddings (contiguous copies) ----
    {
        const float4* Qg = reinterpret_cast<const float4*>(g_Q + (size_t)(bh * N + q0) * DK);
        for (int i = tid; i < 512; i += 256) reinterpret_cast<float4*>(sQ)[i] = Qg[i];
        const float4* rk = reinterpret_cast<const float4*>(relK);
        const float4* rv = reinterpret_cast<const float4*>(relV);
        for (int i = tid; i < 1040; i += 256) {
            reinterpret_cast<float4*>(sRK)[i] = rk[i];
            reinterpret_cast<float4*>(sRV)[i] = rv[i];
        }
    }
    __syncthreads();

    // ---- qrel[q][r] = Q[q,:] . relK[r,:] ----
    for (int p = tid; p < TQ * NR; p += 256) {
        const int q = p / NR;
        const int r = p - q * NR;
        const float4* qv = reinterpret_cast<const float4*>(sQ + q * DK);
        const float4* rv = reinterpret_cast<const float4*>(sRK + r * DK);
        float a = 0.f;
        #pragma unroll
        for (int d = 0; d < 16; d++) {
            float4 x = qv[d], y = rv[d];
            a += x.x * y.x + x.y * y.y + x.z * y.z + x.w * y.w;
        }
        sQr[p] = a;
    }

    // ---- S phase: S[q][k] = (Q.K)/8 + qrel lookup, over 8 chunks of 128 k ----
    const int sty = tid >> 5;   // q = sty*4 + i
    const int stx = tid & 31;   // k = k0 + stx*4 + j
    for (int kt = 0; kt < 8; kt++) {
        const int k0 = kt * 128;
        __syncthreads();
        // load K chunk transposed: sKV[d][128], conflict-free STS (lane -> k)
        const float* Kg = g_K + (size_t)(bh * N + k0) * DK;
        #pragma unroll
        for (int it = 0; it < 8; it++) {
            const int task = warp + it * 8;   // 0..63
            const int dg = task & 15;         // d group (4 dims)
            const int c  = task >> 4;         // k chunk (32 rows)
            const int kk = lane + c * 32;
            float4 v = *reinterpret_cast<const float4*>(Kg + (size_t)kk * DK + dg * 4);
            sKV[(dg * 4 + 0) * 128 + kk] = v.x;
            sKV[(dg * 4 + 1) * 128 + kk] = v.y;
            sKV[(dg * 4 + 2) * 128 + kk] = v.z;
            sKV[(dg * 4 + 3) * 128 + kk] = v.w;
        }
        __syncthreads();

        float acc[4][4] = {};
        #pragma unroll
        for (int d4 = 0; d4 < 16; d4++) {
            const int d = d4 * 4;
            float4 qv[4];
            #pragma unroll
            for (int i = 0; i < 4; i++)
                qv[i] = *reinterpret_cast<const float4*>(sQ + (sty * 4 + i) * DK + d);
            #pragma unroll
            for (int j = 0; j < 4; j++) {
                float4 kv = *reinterpret_cast<const float4*>(sKV + (d + j) * 128 + stx * 4);
                #pragma unroll
                for (int i = 0; i < 4; i++) {
                    const float qq = F4E(qv[i], j);
                    acc[i][0] += qq * kv.x;
                    acc[i][1] += qq * kv.y;
                    acc[i][2] += qq * kv.z;
                    acc[i][3] += qq * kv.w;
                }
            }
        }
        // epilogue: scale + relative bias, float4 store to sS
        const int kbase = k0 + stx * 4;
        #pragma unroll
        for (int i = 0; i < 4; i++) {
            const int q  = sty * 4 + i;
            const int qg = q0 + q;
            float4 r;
            #pragma unroll
            for (int j = 0; j < 4; j++) {
                const int kk = kbase + j;
                int rr = kk - qg;
                rr = rr < -MRP ? -MRP : (rr > MRP ? MRP : rr);
                const float v = acc[i][j] * SCALE + sQr[q * NR + rr + MRP];
                if (j == 0) r.x = v; else if (j == 1) r.y = v;
                else if (j == 2) r.z = v; else r.w = v;
            }
            *reinterpret_cast<float4*>(sS + q * SP + kbase) = r;
        }
    }
    __syncthreads();

    // ---- softmax (8 lanes per row, stride-8, conflict-free) ----
    {
        const int row = tid >> 3;
        const int g   = tid & 7;
        const int qg  = q0 + row;
        float* srow = sS + row * SP;

        float mx = -1e30f;
        for (int j = g; j < N; j += 8) mx = fmaxf(mx, srow[j]);
        #pragma unroll
        for (int o = 1; o < 8; o <<= 1) mx = fmaxf(mx, __shfl_xor_sync(0xffffffffu, mx, o));

        float s = 0.f;
        for (int j = g; j < N; j += 8) {
            const float e = __expf(srow[j] - mx);
            srow[j] = e;
            s += e;
        }
        #pragma unroll
        for (int o = 1; o < 8; o <<= 1) s += __shfl_xor_sync(0xffffffffu, s, o);
        const float inv = 1.f / s;

        float lo = 0.f, hi = 0.f;
        for (int j = g; j < N; j += 8) {
            const float v = srow[j] * inv;
            srow[j] = v;
            if (j <= qg - MRP) lo += v;
            if (j >= qg + MRP) hi += v;
        }
        #pragma unroll
        for (int o = 1; o < 8; o <<= 1) {
            lo += __shfl_xor_sync(0xffffffffu, lo, o);
            hi += __shfl_xor_sync(0xffffffffu, hi, o);
        }
        if (g == 0) {
            sAr[row * NR + 0]       = lo;
            sAr[row * NR + 2 * MRP] = hi;
        }
        __syncthreads();   // normalized sS visible to everyone

        // middle buckets r=1..63: single elements
        for (int r = 1 + g; r < 2 * MRP; r += 8) {
            const int kk = qg + r - MRP;
            sAr[row * NR + r] = (kk >= 0 && kk < N) ? srow[kk] : 0.f;
        }
    }

    // ---- write attn to gmem (coalesced float4) ----
    {
        float* aout = attn_out + (size_t)(bh * N + q0) * N;
        for (int i = tid; i < TQ * N / 4; i += 256) {
            const int rr = i >> 8;     // 256 float4 per row
            const int cc = i & 255;
            float4 v = *reinterpret_cast<const float4*>(sS + rr * SP + cc * 4);
            *reinterpret_cast<float4*>(aout + (size_t)rr * N + cc * 4) = v;
        }
    }

    // ---- V phase: ctx = P @ V (+ rel_v correction) ----
    const int vtx = tid & 15;   // d = vtx*4
    const int vty = tid >> 4;   // q = vty*2
    float4 c0 = {0.f, 0.f, 0.f, 0.f};
    float4 c1 = {0.f, 0.f, 0.f, 0.f};
    for (int kt = 0; kt < 8; kt++) {
        const int k0 = kt * 128;
        __syncthreads();
        const float4* Vg = reinterpret_cast<const float4*>(g_V + (size_t)(bh * N + k0) * DK);
        for (int i = tid; i < 2048; i += 256) reinterpret_cast<float4*>(sKV)[i] = Vg[i];
        __syncthreads();

        const float* p0r = sS + (vty * 2) * SP + k0;
        const float* p1r = p0r + SP;
        #pragma unroll 8
        for (int k4 = 0; k4 < 32; k4++) {
            float4 p0 = *reinterpret_cast<const float4*>(p0r + k4 * 4);
            float4 p1 = *reinterpret_cast<const float4*>(p1r + k4 * 4);
            #pragma unroll
            for (int j = 0; j < 4; j++) {
                float4 vv = *reinterpret_cast<const float4*>(sKV + (k4 * 4 + j) * DK + vtx * 4);
                const float a0 = F4E(p0, j);
                const float a1 = F4E(p1, j);
                c0.x += a0 * vv.x; c0.y += a0 * vv.y; c0.z += a0 * vv.z; c0.w += a0 * vv.w;
                c1.x += a1 * vv.x; c1.y += a1 * vv.y; c1.z += a1 * vv.z; c1.w += a1 * vv.w;
            }
        }
    }
    // rel_v correction: ctx += attn_rel @ rel_v_emb
    {
        const int q = vty * 2;
        #pragma unroll 1
        for (int r = 0; r < NR; r++) {
            const float a0 = sAr[q * NR + r];
            const float a1 = sAr[(q + 1) * NR + r];
            float4 rv = *reinterpret_cast<const float4*>(sRV + r * DK + vtx * 4);
            c0.x += a0 * rv.x; c0.y += a0 * rv.y; c0.z += a0 * rv.z; c0.w += a0 * rv.w;
            c1.x += a1 * rv.x; c1.y += a1 * rv.y; c1.z += a1 * rv.z; c1.w += a1 * rv.w;
        }
    }
    float* cg = g_ctx + (size_t)(bh * N + q0 + vty * 2) * DK + vtx * 4;
    *reinterpret_cast<float4*>(cg)      = c0;
    *reinterpret_cast<float4*>(cg + DK) = c1;
}

// ---------------------------------------------------------------------------
// Kernel 3: output projection  out = ctx_flat @ Wo^T + bo
// ctx gathered from head-major layout.
// ---------------------------------------------------------------------------
__global__ __launch_bounds__(256) void outproj_kernel(
    const float* __restrict__ Wo, const float* __restrict__ bo,
    float* __restrict__ out)
{
    __shared__ float As[16][72];
    __shared__ float Bs[16][72];

    const int m0 = blockIdx.x * 64;
    const int n0 = blockIdx.y * 64;
    const int tid = threadIdx.x;
    const int tx = tid & 15;
    const int ty = tid >> 4;
    const int lr = tid >> 2;
    const int lc = tid & 3;

    float acc[4][4] = {};

    for (int k0 = 0; k0 < Dm; k0 += 16) {
        const int m = m0 + lr;
        const int b = m >> 10;
        const int n = m & 1023;
        const int k = k0 + lc * 4;
        const int h = k >> 6;
        const int dk = k & 63;
        float4 a  = *reinterpret_cast<const float4*>(
            &g_ctx[(size_t)((b * H + h) * N + n) * DK + dk]);
        float4 bw = *reinterpret_cast<const float4*>(&Wo[(size_t)(n0 + lr) * Dm + k0 + lc * 4]);
        __syncthreads();
        As[lc * 4 + 0][lr] = a.x;  As[lc * 4 + 1][lr] = a.y;
        As[lc * 4 + 2][lr] = a.z;  As[lc * 4 + 3][lr] = a.w;
        Bs[lc * 4 + 0][lr] = bw.x; Bs[lc * 4 + 1][lr] = bw.y;
        Bs[lc * 4 + 2][lr] = bw.z; Bs[lc * 4 + 3][lr] = bw.w;
        __syncthreads();
        #pragma unroll
        for (int kk = 0; kk < 16; kk++) {
            float4 av  = *reinterpret_cast<const float4*>(&As[kk][ty * 4]);
            float4 bv4 = *reinterpret_cast<const float4*>(&Bs[kk][tx * 4]);
            #pragma unroll
            for (int i = 0; i < 4; i++) {
                const float aa = F4E(av, i);
                acc[i][0] += aa * bv4.x;
                acc[i][1] += aa * bv4.y;
                acc[i][2] += aa * bv4.z;
                acc[i][3] += aa * bv4.w;
            }
        }
    }

    float4 bb = *reinterpret_cast<const float4*>(&bo[n0 + tx * 4]);
    #pragma unroll
    for (int i = 0; i < 4; i++) {
        const int m = m0 + ty * 4 + i;
        float4 r;
        r.x = acc[i][0] + bb.x;
        r.y = acc[i][1] + bb.y;
        r.z = acc[i][2] + bb.z;
        r.w = acc[i][3] + bb.w;
        *reinterpret_cast<float4*>(&out[(size_t)m * Dm + n0 + tx * 4]) = r;
    }
}

// ---------------------------------------------------------------------------
// Launcher
// ---------------------------------------------------------------------------
extern "C" void kernel_launch(void* const* d_in, const int* in_sizes, int n_in,
                              void* d_out, int out_size)
{
    const float* query = (const float*)d_in[0];
    const float* key   = (const float*)d_in[1];
    const float* value = (const float*)d_in[2];
    const float* Wq = (const float*)d_in[3];
    const float* bq = (const float*)d_in[4];
    const float* Wk = (const float*)d_in[5];
    const float* bk = (const float*)d_in[6];
    const float* Wv = (const float*)d_in[7];
    const float* bv = (const float*)d_in[8];
    const float* Wo = (const float*)d_in[9];
    const float* bo = (const float*)d_in[10];
    const float* relK = (const float*)d_in[11];
    const float* relV = (const float*)d_in[12];

    float* out  = (float*)d_out;
    float* attn = out + (size_t)B * N * Dm;   // second output region

    // QKV projections
    qkv_kernel<<<dim3(64, 16, 3), 256>>>(query, key, value, Wq, bq, Wk, bk, Wv, bv);

    // Fused attention (needs 223 KB dynamic SMEM opt-in)
    static_assert(SMEM_FLOATS * 4 <= 232448, "smem over limit");
    cudaFuncSetAttribute(attn_kernel, cudaFuncAttributeMaxDynamicSharedMemorySize,
                         SMEM_FLOATS * 4);
    attn_kernel<<<dim3(N / TQ, BH), 256, SMEM_FLOATS * 4>>>(relK, relV, attn);

    // Output projection
    outproj_kernel<<<dim3(64, 16), 256>>>(Wo, bo, out);
}

// round 3
// speedup vs baseline: 1.1406x; 1.1406x over previous
#include <cuda_runtime.h>

// Problem constants
constexpr int B   = 4;
constexpr int N   = 1024;
constexpr int Dm  = 1024;
constexpr int H   = 16;
constexpr int DK  = 64;
constexpr int MRP = 32;
constexpr int NR  = 2 * MRP + 1;   // 65
constexpr int BH  = B * H;         // 64
constexpr float SCALE = 0.125f;    // 1/sqrt(64)

// Scratch (static device globals; no allocation allowed)
__device__ float g_Q[BH * N * DK];
__device__ float g_K[BH * N * DK];
__device__ float g_V[BH * N * DK];
__device__ float g_ctx[BH * N * DK];

#define F4E(v, j) ((j) == 0 ? (v).x : (j) == 1 ? (v).y : (j) == 2 ? (v).z : (v).w)

// ---- packed fp32x2 helpers (B300: FFMA2 reachable only via PTX) ----
__device__ __forceinline__ unsigned long long dup2(float x) {
    unsigned long long r;
    asm("mov.b64 %0, {%1, %1};" : "=l"(r) : "f"(x));
    return r;
}
__device__ __forceinline__ void fma2(unsigned long long& d,
                                     unsigned long long a, unsigned long long b) {
    asm("fma.rn.f32x2 %0, %1, %2, %0;" : "+l"(d) : "l"(a), "l"(b));
}
__device__ __forceinline__ float lo2(unsigned long long v) {
    return __uint_as_float((unsigned)v);
}
__device__ __forceinline__ float hi2(unsigned long long v) {
    return __uint_as_float((unsigned)(v >> 32));
}

// ---------------------------------------------------------------------------
// Kernel 1: QKV projections.  Y = X @ W^T + b, scattered to head-major
// [bh][n][dk].  Tiled SGEMM 128x128x16, 256 threads, 8x8 micro-tile, f32x2.
// ---------------------------------------------------------------------------
__global__ __launch_bounds__(256, 2) void qkv_kernel(
    const float* __restrict__ q_in, const float* __restrict__ k_in,
    const float* __restrict__ v_in,
    const float* __restrict__ Wq, const float* __restrict__ bq,
    const float* __restrict__ Wk, const float* __restrict__ bk,
    const float* __restrict__ Wv, const float* __restrict__ bv)
{
    const int which = blockIdx.z;
    const float* X    = which == 0 ? q_in : which == 1 ? k_in : v_in;
    const float* W    = which == 0 ? Wq   : which == 1 ? Wk   : Wv;
    const float* bias = which == 0 ? bq   : which == 1 ? bk   : bv;
    float* out        = which == 0 ? g_Q  : which == 1 ? g_K  : g_V;

    __shared__ float As[16][132];
    __shared__ float Bs[16][132];

    const int m0 = blockIdx.x * 128;
    const int n0 = blockIdx.y * 128;
    const int tid = threadIdx.x;
    const int tx = tid & 15;       // n direction (8 each)
    const int ty = tid >> 4;       // m direction (8 each)
    const int lr = tid >> 2;       // load row (0..63)
    const int lc = tid & 3;        // load float4 col group

    unsigned long long acc[8][4] = {};

    const float* xr0 = X + (size_t)(m0 + lr) * Dm + lc * 4;
    const float* xr1 = xr0 + (size_t)64 * Dm;
    const float* wr0 = W + (size_t)(n0 + lr) * Dm + lc * 4;
    const float* wr1 = wr0 + (size_t)64 * Dm;

    for (int k0 = 0; k0 < Dm; k0 += 16) {
        float4 a0 = *reinterpret_cast<const float4*>(xr0 + k0);
        float4 a1 = *reinterpret_cast<const float4*>(xr1 + k0);
        float4 b0 = *reinterpret_cast<const float4*>(wr0 + k0);
        float4 b1 = *reinterpret_cast<const float4*>(wr1 + k0);
        __syncthreads();
        As[lc * 4 + 0][lr] = a0.x;      As[lc * 4 + 1][lr] = a0.y;
        As[lc * 4 + 2][lr] = a0.z;      As[lc * 4 + 3][lr] = a0.w;
        As[lc * 4 + 0][lr + 64] = a1.x; As[lc * 4 + 1][lr + 64] = a1.y;
        As[lc * 4 + 2][lr + 64] = a1.z; As[lc * 4 + 3][lr + 64] = a1.w;
        Bs[lc * 4 + 0][lr] = b0.x;      Bs[lc * 4 + 1][lr] = b0.y;
        Bs[lc * 4 + 2][lr] = b0.z;      Bs[lc * 4 + 3][lr] = b0.w;
        Bs[lc * 4 + 0][lr + 64] = b1.x; Bs[lc * 4 + 1][lr + 64] = b1.y;
        Bs[lc * 4 + 2][lr + 64] = b1.z; Bs[lc * 4 + 3][lr + 64] = b1.w;
        __syncthreads();
        #pragma unroll
        for (int kk = 0; kk < 16; kk++) {
            float4 av0 = *reinterpret_cast<const float4*>(&As[kk][ty * 8]);
            float4 av1 = *reinterpret_cast<const float4*>(&As[kk][ty * 8 + 4]);
            ulonglong2 bb0 = *reinterpret_cast<const ulonglong2*>(&Bs[kk][tx * 8]);
            ulonglong2 bb1 = *reinterpret_cast<const ulonglong2*>(&Bs[kk][tx * 8 + 4]);
            unsigned long long ad[8];
            ad[0] = dup2(av0.x); ad[1] = dup2(av0.y);
            ad[2] = dup2(av0.z); ad[3] = dup2(av0.w);
            ad[4] = dup2(av1.x); ad[5] = dup2(av1.y);
            ad[6] = dup2(av1.z); ad[7] = dup2(av1.w);
            #pragma unroll
            for (int i = 0; i < 8; i++) {
                fma2(acc[i][0], ad[i], bb0.x);
                fma2(acc[i][1], ad[i], bb0.y);
                fma2(acc[i][2], ad[i], bb1.x);
                fma2(acc[i][3], ad[i], bb1.y);
            }
        }
    }

    const int o0 = n0 + tx * 8;
    const int h  = o0 >> 6;
    const int dk = o0 & 63;
    float4 bi0 = *reinterpret_cast<const float4*>(&bias[o0]);
    float4 bi1 = *reinterpret_cast<const float4*>(&bias[o0 + 4]);
    #pragma unroll
    for (int i = 0; i < 8; i++) {
        const int m = m0 + ty * 8 + i;
        const int b = m >> 10;
        const int n = m & 1023;
        float4 r0, r1;
        r0.x = lo2(acc[i][0]) + bi0.x; r0.y = hi2(acc[i][0]) + bi0.y;
        r0.z = lo2(acc[i][1]) + bi0.z; r0.w = hi2(acc[i][1]) + bi0.w;
        r1.x = lo2(acc[i][2]) + bi1.x; r1.y = hi2(acc[i][2]) + bi1.y;
        r1.z = lo2(acc[i][3]) + bi1.z; r1.w = hi2(acc[i][3]) + bi1.w;
        float* p = &out[(size_t)((b * H + h) * N + n) * DK + dk];
        *reinterpret_cast<float4*>(p)     = r0;
        *reinterpret_cast<float4*>(p + 4) = r1;
    }
}

// ---------------------------------------------------------------------------
// Kernel 2: fused attention per (bh, 32-row q-tile).
// ---------------------------------------------------------------------------
constexpr int TQ = 32;
constexpr int SP = 1032;   // sS row pitch in floats

constexpr int O_S  = 0;
constexpr int O_KV = O_S  + TQ * SP;
constexpr int O_Q  = O_KV + 8192;
constexpr int O_RK = O_Q  + 2048;
constexpr int O_RV = O_RK + 4160;
constexpr int O_QR = O_RV + 4160;
constexpr int O_AR = O_QR + 2080;
constexpr int SMEM_FLOATS = O_AR + 2080; // 55744 floats = 222976 bytes

__global__ __launch_bounds__(256) void attn_kernel(
    const float* __restrict__ relK, const float* __restrict__ relV,
    float* __restrict__ attn_out)
{
    extern __shared__ float sm[];
    float* sS  = sm + O_S;
    float* sKV = sm + O_KV;
    float* sQ  = sm + O_Q;
    float* sRK = sm + O_RK;
    float* sRV = sm + O_RV;
    float* sQr = sm + O_QR;
    float* sAr = sm + O_AR;

    const int bh = blockIdx.y;
    const int q0 = blockIdx.x * TQ;
    const int tid  = threadIdx.x;
    const int warp = tid >> 5;
    const int lane = tid & 31;

    // ---- load Q tile and rel embeddings ----
    {
        const float4* Qg = reinterpret_cast<const float4*>(g_Q + (size_t)(bh * N + q0) * DK);
        for (int i = tid; i < 512; i += 256) reinterpret_cast<float4*>(sQ)[i] = Qg[i];
        const float4* rk = reinterpret_cast<const float4*>(relK);
        const float4* rv = reinterpret_cast<const float4*>(relV);
        for (int i = tid; i < 1040; i += 256) {
            reinterpret_cast<float4*>(sRK)[i] = rk[i];
            reinterpret_cast<float4*>(sRV)[i] = rv[i];
        }
    }
    __syncthreads();

    // ---- qrel[q][r] = Q[q,:] . relK[r,:] ----
    for (int p = tid; p < TQ * NR; p += 256) {
        const int q = p / NR;
        const int r = p - q * NR;
        const float4* qv = reinterpret_cast<const float4*>(sQ + q * DK);
        const float4* rv = reinterpret_cast<const float4*>(sRK + r * DK);
        float a = 0.f;
        #pragma unroll
        for (int d = 0; d < 16; d++) {
            float4 x = qv[d], y = rv[d];
            a += x.x * y.x + x.y * y.y + x.z * y.z + x.w * y.w;
        }
        sQr[p] = a;
    }

    // ---- S phase ----
    const int sty = tid >> 5;   // q = sty*4 + i
    const int stx = tid & 31;   // k = k0 + stx*4 + j
    for (int kt = 0; kt < 8; kt++) {
        const int k0 = kt * 128;
        __syncthreads();
        const float* Kg = g_K + (size_t)(bh * N + k0) * DK;
        #pragma unroll
        for (int it = 0; it < 8; it++) {
            const int task = warp + it * 8;
            const int dg = task & 15;
            const int c  = task >> 4;
            const int kk = lane + c * 32;
            float4 v = *reinterpret_cast<const float4*>(Kg + (size_t)kk * DK + dg * 4);
            sKV[(dg * 4 + 0) * 128 + kk] = v.x;
            sKV[(dg * 4 + 1) * 128 + kk] = v.y;
            sKV[(dg * 4 + 2) * 128 + kk] = v.z;
            sKV[(dg * 4 + 3) * 128 + kk] = v.w;
        }
        __syncthreads();

        unsigned long long acc2[4][2] = {};
        #pragma unroll
        for (int d4 = 0; d4 < 16; d4++) {
            const int d = d4 * 4;
            float4 qv[4];
            #pragma unroll
            for (int i = 0; i < 4; i++)
                qv[i] = *reinterpret_cast<const float4*>(sQ + (sty * 4 + i) * DK + d);
            #pragma unroll
            for (int j = 0; j < 4; j++) {
                ulonglong2 kv = *reinterpret_cast<const ulonglong2*>(
                    sKV + (d + j) * 128 + stx * 4);
                #pragma unroll
                for (int i = 0; i < 4; i++) {
                    unsigned long long qd = dup2(F4E(qv[i], j));
                    fma2(acc2[i][0], qd, kv.x);
                    fma2(acc2[i][1], qd, kv.y);
                }
            }
        }
        // epilogue: scale + relative bias
        const int kbase = k0 + stx * 4;
        #pragma unroll
        for (int i = 0; i < 4; i++) {
            const int q  = sty * 4 + i;
            const int qg = q0 + q;
            float vals[4] = { lo2(acc2[i][0]), hi2(acc2[i][0]),
                              lo2(acc2[i][1]), hi2(acc2[i][1]) };
            float4 r;
            #pragma unroll
            for (int j = 0; j < 4; j++) {
                const int kk = kbase + j;
                int rr = kk - qg;
                rr = rr < -MRP ? -MRP : (rr > MRP ? MRP : rr);
                const float v = vals[j] * SCALE + sQr[q * NR + rr + MRP];
                if (j == 0) r.x = v; else if (j == 1) r.y = v;
                else if (j == 2) r.z = v; else r.w = v;
            }
            *reinterpret_cast<float4*>(sS + q * SP + kbase) = r;
        }
    }
    __syncthreads();

    // ---- softmax (8 lanes per row) ----
    {
        const int row = tid >> 3;
        const int g   = tid & 7;
        const int qg  = q0 + row;
        float* srow = sS + row * SP;

        float mx = -1e30f;
        for (int j = g; j < N; j += 8) mx = fmaxf(mx, srow[j]);
        #pragma unroll
        for (int o = 1; o < 8; o <<= 1) mx = fmaxf(mx, __shfl_xor_sync(0xffffffffu, mx, o));

        float s = 0.f;
        for (int j = g; j < N; j += 8) {
            const float e = __expf(srow[j] - mx);
            srow[j] = e;
            s += e;
        }
        #pragma unroll
        for (int o = 1; o < 8; o <<= 1) s += __shfl_xor_sync(0xffffffffu, s, o);
        const float inv = 1.f / s;

        float lo = 0.f, hi = 0.f;
        for (int j = g; j < N; j += 8) {
            const float v = srow[j] * inv;
            srow[j] = v;
            if (j <= qg - MRP) lo += v;
            if (j >= qg + MRP) hi += v;
        }
        #pragma unroll
        for (int o = 1; o < 8; o <<= 1) {
            lo += __shfl_xor_sync(0xffffffffu, lo, o);
            hi += __shfl_xor_sync(0xffffffffu, hi, o);
        }
        if (g == 0) {
            sAr[row * NR + 0]       = lo;
            sAr[row * NR + 2 * MRP] = hi;
        }
        __syncthreads();

        for (int r = 1 + g; r < 2 * MRP; r += 8) {
            const int kk = qg + r - MRP;
            sAr[row * NR + r] = (kk >= 0 && kk < N) ? srow[kk] : 0.f;
        }
    }

    // ---- write attn to gmem ----
    {
        float* aout = attn_out + (size_t)(bh * N + q0) * N;
        for (int i = tid; i < TQ * N / 4; i += 256) {
            const int rr = i >> 8;
            const int cc = i & 255;
            float4 v = *reinterpret_cast<const float4*>(sS + rr * SP + cc * 4);
            *reinterpret_cast<float4*>(aout + (size_t)rr * N + cc * 4) = v;
        }
    }

    // ---- V phase: ctx = P @ V (+ rel_v correction), f32x2 ----
    const int vtx = tid & 15;   // d = vtx*4
    const int vty = tid >> 4;   // q = vty*2
    unsigned long long c0p[2] = {}, c1p[2] = {};
    for (int kt = 0; kt < 8; kt++) {
        const int k0 = kt * 128;
        __syncthreads();
        const float4* Vg = reinterpret_cast<const float4*>(g_V + (size_t)(bh * N + k0) * DK);
        for (int i = tid; i < 2048; i += 256) reinterpret_cast<float4*>(sKV)[i] = Vg[i];
        __syncthreads();

        const float* p0r = sS + (vty * 2) * SP + k0;
        const float* p1r = p0r + SP;
        #pragma unroll 8
        for (int k4 = 0; k4 < 32; k4++) {
            float4 p0 = *reinterpret_cast<const float4*>(p0r + k4 * 4);
            float4 p1 = *reinterpret_cast<const float4*>(p1r + k4 * 4);
            #pragma unroll
            for (int j = 0; j < 4; j++) {
                ulonglong2 vv = *reinterpret_cast<const ulonglong2*>(
                    sKV + (k4 * 4 + j) * DK + vtx * 4);
                unsigned long long a0 = dup2(F4E(p0, j));
                unsigned long long a1 = dup2(F4E(p1, j));
                fma2(c0p[0], a0, vv.x); fma2(c0p[1], a0, vv.y);
                fma2(c1p[0], a1, vv.x); fma2(c1p[1], a1, vv.y);
            }
        }
    }
    // rel_v correction
    {
        const int q = vty * 2;
        #pragma unroll 1
        for (int r = 0; r < NR; r++) {
            unsigned long long a0 = dup2(sAr[q * NR + r]);
            unsigned long long a1 = dup2(sAr[(q + 1) * NR + r]);
            ulonglong2 rv = *reinterpret_cast<const ulonglong2*>(sRV + r * DK + vtx * 4);
            fma2(c0p[0], a0, rv.x); fma2(c0p[1], a0, rv.y);
            fma2(c1p[0], a1, rv.x); fma2(c1p[1], a1, rv.y);
        }
    }
    float4 c0, c1;
    c0.x = lo2(c0p[0]); c0.y = hi2(c0p[0]); c0.z = lo2(c0p[1]); c0.w = hi2(c0p[1]);
    c1.x = lo2(c1p[0]); c1.y = hi2(c1p[0]); c1.z = lo2(c1p[1]); c1.w = hi2(c1p[1]);
    float* cg = g_ctx + (size_t)(bh * N + q0 + vty * 2) * DK + vtx * 4;
    *reinterpret_cast<float4*>(cg)      = c0;
    *reinterpret_cast<float4*>(cg + DK) = c1;
}

// ---------------------------------------------------------------------------
// Kernel 3: output projection  out = ctx_flat @ Wo^T + bo (128x128, f32x2)
// ---------------------------------------------------------------------------
__global__ __launch_bounds__(256, 2) void outproj_kernel(
    const float* __restrict__ Wo, const float* __restrict__ bo,
    float* __restrict__ out)
{
    __shared__ float As[16][132];
    __shared__ float Bs[16][132];

    const int m0 = blockIdx.x * 128;
    const int n0 = blockIdx.y * 128;
    const int tid = threadIdx.x;
    const int tx = tid & 15;
    const int ty = tid >> 4;
    const int lr = tid >> 2;
    const int lc = tid & 3;

    unsigned long long acc[8][4] = {};

    // ctx row addressing (gather from head-major layout)
    const int m_a0 = m0 + lr;
    const int m_a1 = m_a0 + 64;
    const int ba0 = m_a0 >> 10, na0 = m_a0 & 1023;
    const int ba1 = m_a1 >> 10, na1 = m_a1 & 1023;
    const float* wr0 = Wo + (size_t)(n0 + lr) * Dm + lc * 4;
    const float* wr1 = wr0 + (size_t)64 * Dm;

    for (int k0 = 0; k0 < Dm; k0 += 16) {
        const int k = k0 + lc * 4;
        const int h = k >> 6;
        const int dk = k & 63;
        float4 a0 = *reinterpret_cast<const float4*>(
            &g_ctx[(size_t)((ba0 * H + h) * N + na0) * DK + dk]);
        float4 a1 = *reinterpret_cast<const float4*>(
            &g_ctx[(size_t)((ba1 * H + h) * N + na1) * DK + dk]);
        float4 b0 = *reinterpret_cast<const float4*>(wr0 + k0);
        float4 b1 = *reinterpret_cast<const float4*>(wr1 + k0);
        __syncthreads();
        As[lc * 4 + 0][lr] = a0.x;      As[lc * 4 + 1][lr] = a0.y;
        As[lc * 4 + 2][lr] = a0.z;      As[lc * 4 + 3][lr] = a0.w;
        As[lc * 4 + 0][lr + 64] = a1.x; As[lc * 4 + 1][lr + 64] = a1.y;
        As[lc * 4 + 2][lr + 64] = a1.z; As[lc * 4 + 3][lr + 64] = a1.w;
        Bs[lc * 4 + 0][lr] = b0.x;      Bs[lc * 4 + 1][lr] = b0.y;
        Bs[lc * 4 + 2][lr] = b0.z;      Bs[lc * 4 + 3][lr] = b0.w;
        Bs[lc * 4 + 0][lr + 64] = b1.x; Bs[lc * 4 + 1][lr + 64] = b1.y;
        Bs[lc * 4 + 2][lr + 64] = b1.z; Bs[lc * 4 + 3][lr + 64] = b1.w;
        __syncthreads();
        #pragma unroll
        for (int kk = 0; kk < 16; kk++) {
            float4 av0 = *reinterpret_cast<const float4*>(&As[kk][ty * 8]);
            float4 av1 = *reinterpret_cast<const float4*>(&As[kk][ty * 8 + 4]);
            ulonglong2 bb0 = *reinterpret_cast<const ulonglong2*>(&Bs[kk][tx * 8]);
            ulonglong2 bb1 = *reinterpret_cast<const ulonglong2*>(&Bs[kk][tx * 8 + 4]);
            unsigned long long ad[8];
            ad[0] = dup2(av0.x); ad[1] = dup2(av0.y);
            ad[2] = dup2(av0.z); ad[3] = dup2(av0.w);
            ad[4] = dup2(av1.x); ad[5] = dup2(av1.y);
            ad[6] = dup2(av1.z); ad[7] = dup2(av1.w);
            #pragma unroll
            for (int i = 0; i < 8; i++) {
                fma2(acc[i][0], ad[i], bb0.x);
                fma2(acc[i][1], ad[i], bb0.y);
                fma2(acc[i][2], ad[i], bb1.x);
                fma2(acc[i][3], ad[i], bb1.y);
            }
        }
    }

    const int o0 = n0 + tx * 8;
    float4 bi0 = *reinterpret_cast<const float4*>(&bo[o0]);
    float4 bi1 = *reinterpret_cast<const float4*>(&bo[o0 + 4]);
    #pragma unroll
    for (int i = 0; i < 8; i++) {
        const int m = m0 + ty * 8 + i;
        float4 r0, r1;
        r0.x = lo2(acc[i][0]) + bi0.x; r0.y = hi2(acc[i][0]) + bi0.y;
        r0.z = lo2(acc[i][1]) + bi0.z; r0.w = hi2(acc[i][1]) + bi0.w;
        r1.x = lo2(acc[i][2]) + bi1.x; r1.y = hi2(acc[i][2]) + bi1.y;
        r1.z = lo2(acc[i][3]) + bi1.z; r1.w = hi2(acc[i][3]) + bi1.w;
        float* p = &out[(size_t)m * Dm + o0];
        *reinterpret_cast<float4*>(p)     = r0;
        *reinterpret_cast<float4*>(p + 4) = r1;
    }
}

// ---------------------------------------------------------------------------
// Launcher
// ---------------------------------------------------------------------------
extern "C" void kernel_launch(void* const* d_in, const int* in_sizes, int n_in,
                              void* d_out, int out_size)
{
    const float* query = (const float*)d_in[0];
    const float* key   = (const float*)d_in[1];
    const float* value = (const float*)d_in[2];
    const float* Wq = (const float*)d_in[3];
    const float* bq = (const float*)d_in[4];
    const float* Wk = (const float*)d_in[5];
    const float* bk = (const float*)d_in[6];
    const float* Wv = (const float*)d_in[7];
    const float* bv = (const float*)d_in[8];
    const float* Wo = (const float*)d_in[9];
    const float* bo = (const float*)d_in[10];
    const float* relK = (const float*)d_in[11];
    const float* relV = (const float*)d_in[12];

    float* out  = (float*)d_out;
    float* attn = out + (size_t)B * N * Dm;   // second output region

    // QKV projections (128x128 tiles)
    qkv_kernel<<<dim3(32, 8, 3), 256>>>(query, key, value, Wq, bq, Wk, bk, Wv, bv);

    // Fused attention (223 KB dynamic SMEM opt-in)
    static_assert(SMEM_FLOATS * 4 <= 232448, "smem over limit");
    cudaFuncSetAttribute(attn_kernel, cudaFuncAttributeMaxDynamicSharedMemorySize,
                         SMEM_FLOATS * 4);
    attn_kernel<<<dim3(N / TQ, BH), 256, SMEM_FLOATS * 4>>>(relK, relV, attn);

    // Output projection
    outproj_kernel<<<dim3(32, 8), 256>>>(Wo, bo, out);
}